// round 7
// baseline (speedup 1.0000x reference)
#include <cuda_runtime.h>
#include <cstdint>

#define H        768
#define CK       16                    // K floats per pipeline stage (64 B/row)
#define NCH      (H / CK)              // 48 chunks
#define DEPTH    2                     // cp.async ring stages
#define WROWS    64                    // rows per warp pass (2 per lane)
#define G        2                     // rows per lane
#define RSTRIDE  20                    // floats per row slot (16 + 4 pad; conflict-free)
#define ROWB     (RSTRIDE * 4)         // 80 B
#define CHUNK_FLOATS (WROWS * RSTRIDE) // 1280
#define CHUNK_BYTES  (CHUNK_FLOATS * 4)  // 5120
#define WARPS    16                    // warps per CTA (512 threads), 1 CTA/SM
#define W_SLOTS  (H * 5)               // weight float4 slots in smem (60 KB)
#define W_FLOATS (W_SLOTS * 4)
#define SMEM_BYTES (W_SLOTS * 16 + WARPS * DEPTH * CHUNK_BYTES)  // 225280 B

// 17 fused channels: a0,a1 | b0..b3 | c1_0,c1_1 | c2_0..2 | c3_0..3 | c4_0,c4_1
__constant__ float c_bias[17];

__device__ float4 g_pack4[H * 4];      // channels 0..15, [k][p]
__device__ float  g_pack1[H];          // channel 16
__device__ float  g_biasStage[17];
__device__ unsigned int g_ticket;

// ---------------------------------------------------------------------------
__global__ void prep_kernel(
    const float* __restrict__ Wa,  const float* __restrict__ ba,
    const float* __restrict__ Wb,  const float* __restrict__ bb,
    const float* __restrict__ Wc1, const float* __restrict__ bc1,
    const float* __restrict__ Wc2, const float* __restrict__ bc2,
    const float* __restrict__ Wc3, const float* __restrict__ bc3,
    const float* __restrict__ Wc4, const float* __restrict__ bc4)
{
    int id = blockIdx.x * blockDim.x + threadIdx.x;
    if (id == 0) g_ticket = 0u;

    auto getw = [&](int ch, int k) -> float {
        if (ch < 2)  return Wa [ ch        * H + k];
        if (ch < 6)  return Wb [(ch - 2)  * H + k];
        if (ch < 8)  return Wc1[(ch - 6)  * H + k];
        if (ch < 11) return Wc2[(ch - 8)  * H + k];
        if (ch < 15) return Wc3[(ch - 11) * H + k];
        return Wc4[(ch - 15) * H + k];
    };

    if (id < H * 4) {
        int k = id >> 2, p = id & 3;
        g_pack4[id] = make_float4(getw(4 * p, k),     getw(4 * p + 1, k),
                                  getw(4 * p + 2, k), getw(4 * p + 3, k));
    }
    if (id < H) g_pack1[id] = getw(16, id);
    if (id < 17) {
        int ch = id; float b;
        if      (ch < 2)  b = ba [ch];
        else if (ch < 6)  b = bb [ch - 2];
        else if (ch < 8)  b = bc1[ch - 6];
        else if (ch < 11) b = bc2[ch - 8];
        else if (ch < 15) b = bc3[ch - 11];
        else              b = bc4[ch - 15];
        g_biasStage[ch] = b;
    }
}

// ---------------------------------------------------------------------------
__device__ __forceinline__ void ffma2(float2& d, const float2 a, const float2 b)
{
    asm("fma.rn.f32x2 %0, %1, %2, %0;"
        : "+l"(reinterpret_cast<unsigned long long&>(d))
        : "l"(reinterpret_cast<const unsigned long long&>(a)),
          "l"(reinterpret_cast<const unsigned long long&>(b)));
}

__device__ __forceinline__ void cp16(uint32_t saddr, const void* gptr)
{
    asm volatile("cp.async.cg.shared.global [%0], [%1], 16;"
                 :: "r"(saddr), "l"(gptr) : "memory");
}
__device__ __forceinline__ void cp_commit()
{
    asm volatile("cp.async.commit_group;" ::: "memory");
}
template <int N>
__device__ __forceinline__ void cp_wait()
{
    asm volatile("cp.async.wait_group %0;" :: "n"(N) : "memory");
}

// ---------------------------------------------------------------------------
// 64-row pass per warp (2 rows/lane); warp-private 2-deep cp.async ring for x;
// weights resident in shared memory (broadcast LDS). 16 warps/SM (4/SMSP)
// for latency hiding; warp-level ticket over 2048 passes.
// ---------------------------------------------------------------------------
extern __shared__ float smem[];

__global__ void __launch_bounds__(WARPS * 32, 1)
main_kernel(const float* __restrict__ x, float* __restrict__ out, int B, int npasses)
{
    const int wid  = threadIdx.x >> 5;
    const int lane = threadIdx.x & 31;

    float4* sw    = reinterpret_cast<float4*>(smem);        // [H][5] float4
    float*  xbase = smem + W_FLOATS;

    // ---- stage weights into smem once per CTA ----
    for (int i = threadIdx.x; i < W_SLOTS; i += WARPS * 32) {
        const int k = i / 5, p = i - k * 5;
        sw[i] = (p < 4) ? g_pack4[k * 4 + p]
                        : make_float4(g_pack1[k], 0.f, 0.f, 0.f);
    }
    __syncthreads();

    const uint32_t sb = (uint32_t)__cvta_generic_to_shared(xbase)
                        + wid * (DEPTH * CHUNK_BYTES);
    float* xw = xbase + wid * (DEPTH * CHUNK_FLOATS);

    // cp.async mapping: 4 lanes x 16 B cover one 64 B row segment; 8 rows/inst
    const int crow  = lane >> 2;   // 0..7
    const int cpart = lane & 3;    // 0..3

    for (;;) {
        unsigned t;
        if (lane == 0) t = atomicAdd(&g_ticket, 1u);
        t = __shfl_sync(0xffffffffu, t, 0);
        if (t >= (unsigned)npasses) break;

        const int    row0 = (int)t * WROWS;
        const float* gx   = x + (size_t)row0 * H;

        auto load_chunk = [&](int c, int d) {
            const float*   gsrc = gx + c * CK + (size_t)crow * H + cpart * 4;
            const uint32_t dst0 = sb + d * CHUNK_BYTES + crow * ROWB + cpart * 16;
            #pragma unroll
            for (int i = 0; i < 8; ++i) {          // 8 x 8 rows = 64 rows
                if (row0 + i * 8 + crow < B)
                    cp16(dst0 + i * 8 * ROWB, gsrc + (size_t)(i * 8) * H);
            }
        };

        float2 acc[G][8];
        float  a16[G];
        #pragma unroll
        for (int g = 0; g < G; ++g) {
            #pragma unroll
            for (int p = 0; p < 8; ++p) acc[g][p] = make_float2(0.f, 0.f);
            a16[g] = 0.f;
        }

        cp_wait<0>();                 // drain leftover groups from prior pass
        load_chunk(0, 0); cp_commit();
        load_chunk(1, 1); cp_commit();

        #pragma unroll 2
        for (int c = 0; c < NCH; ++c) {
            cp_wait<DEPTH - 1>();     // chunk c resident
            __syncwarp();

            const float* xb = xw + (c & 1) * CHUNK_FLOATS;
            const int kc = c * CK;
            #pragma unroll
            for (int rg = 0; rg < 4; ++rg) {
                float4 xv[G];
                #pragma unroll
                for (int g = 0; g < G; ++g)
                    xv[g] = *reinterpret_cast<const float4*>(
                        xb + (lane + 32 * g) * RSTRIDE + rg * 4);

                const int kb = kc + rg * 4;
                #pragma unroll
                for (int j = 0; j < 4; ++j) {
                    const float4* wk = sw + (kb + j) * 5;   // warp-uniform -> broadcast LDS
                    const float4 w0 = wk[0];
                    const float4 w1 = wk[1];
                    const float4 w2 = wk[2];
                    const float4 w3 = wk[3];
                    const float  wl = wk[4].x;
                    #pragma unroll
                    for (int g = 0; g < G; ++g) {
                        const float xk = (j == 0) ? xv[g].x : (j == 1) ? xv[g].y
                                       : (j == 2) ? xv[g].z : xv[g].w;
                        const float2 xd = make_float2(xk, xk);
                        ffma2(acc[g][0], xd, make_float2(w0.x, w0.y));
                        ffma2(acc[g][1], xd, make_float2(w0.z, w0.w));
                        ffma2(acc[g][2], xd, make_float2(w1.x, w1.y));
                        ffma2(acc[g][3], xd, make_float2(w1.z, w1.w));
                        ffma2(acc[g][4], xd, make_float2(w2.x, w2.y));
                        ffma2(acc[g][5], xd, make_float2(w2.z, w2.w));
                        ffma2(acc[g][6], xd, make_float2(w3.x, w3.y));
                        ffma2(acc[g][7], xd, make_float2(w3.z, w3.w));
                        a16[g] = fmaf(xk, wl, a16[g]);
                    }
                }
            }
            __syncwarp();

            if (c + DEPTH < NCH) load_chunk(c + DEPTH, c & 1);
            cp_commit();              // empty groups keep wait_group counts exact
        }

        // --- epilogue: bias, routing, masked scattered stores (2 rows/lane) ---
        #pragma unroll
        for (int g = 0; g < G; ++g) {
            const int r = row0 + lane + 32 * g;
            if (r >= B) continue;

            float v[17];
            #pragma unroll
            for (int p = 0; p < 8; ++p) {
                v[2 * p]     = acc[g][p].x + c_bias[2 * p];
                v[2 * p + 1] = acc[g][p].y + c_bias[2 * p + 1];
            }
            v[16] = a16[g] + c_bias[16];

            const bool active = v[1] > v[0];               // argmax(out_a) != 0

            ((float2*)out)[r] = make_float2(v[0], v[1]);   // out_a

            int pb = 0; float best = v[2];
            if (v[3] > best) { pb = 1; best = v[3]; }
            if (v[4] > best) { pb = 2; best = v[4]; }
            if (v[5] > best) { pb = 3; best = v[5]; }

            float* ob = out + 2 * (size_t)B + 5 * (size_t)r;   // out_b
            ob[0] = 0.0f;
            #pragma unroll
            for (int j = 0; j < 4; ++j) ob[j + 1] = active ? v[2 + j] : 0.0f;

            float* oc = out + 7 * (size_t)B + 11 * (size_t)r;  // out_c
            #pragma unroll
            for (int j = 0; j < 11; ++j) {
                const int hd = (j < 2) ? 0 : (j < 5) ? 1 : (j < 9) ? 2 : 3;
                oc[j] = (active && hd == pb) ? v[6 + j] : 0.0f;
            }
        }
    }
}

// ---------------------------------------------------------------------------
extern "C" void kernel_launch(void* const* d_in, const int* in_sizes, int n_in,
                              void* d_out, int out_size)
{
    const float* x = (const float*)d_in[0];
    const int B = in_sizes[0] / H;

    prep_kernel<<<12, 256>>>(
        (const float*)d_in[1],  (const float*)d_in[2],
        (const float*)d_in[3],  (const float*)d_in[4],
        (const float*)d_in[5],  (const float*)d_in[6],
        (const float*)d_in[7],  (const float*)d_in[8],
        (const float*)d_in[9],  (const float*)d_in[10],
        (const float*)d_in[11], (const float*)d_in[12]);

    void* pb = nullptr; cudaGetSymbolAddress(&pb, g_biasStage);
    cudaMemcpyToSymbolAsync(c_bias, pb, sizeof(float) * 17, 0,
                            cudaMemcpyDeviceToDevice, 0);

    const int npasses = (B + WROWS - 1) / WROWS;   // 2048 for B=131072
    const int grid    = 148;                        // 1 CTA/SM, 2368 warp slots

    cudaFuncSetAttribute(main_kernel,
                         cudaFuncAttributeMaxDynamicSharedMemorySize, SMEM_BYTES);
    main_kernel<<<grid, WARPS * 32, SMEM_BYTES>>>(x, (float*)d_out, B, npasses);
}

// round 8
// speedup vs baseline: 1.7004x; 1.7004x over previous
#include <cuda_runtime.h>
#include <cstdint>

#define H        768
#define CK       16                    // K floats per pipeline stage (64 B/row)
#define NCH      (H / CK)              // 48 chunks
#define DEPTH    2                     // cp.async ring stages
#define WROWS    128                   // rows per warp pass (4 per lane)
#define G        4                     // rows per lane
#define RSTRIDE  20                    // floats per row slot (16 + 4 pad; conflict-free)
#define ROWB     (RSTRIDE * 4)         // 80 B
#define CHUNK_FLOATS (WROWS * RSTRIDE) // 2560
#define CHUNK_BYTES  (CHUNK_FLOATS * 4)
#define WARPS    8                     // warps per CTA (256 threads), 1 CTA/SM
#define W_SLOTS  (H * 5)               // weight float4 slots in smem (60 KB)
#define W_FLOATS (W_SLOTS * 4)
#define SMEM_BYTES (W_SLOTS * 16 + WARPS * DEPTH * CHUNK_BYTES)  // 225280 B

// 17 fused channels: a0,a1 | b0..b3 | c1_0,c1_1 | c2_0..2 | c3_0..3 | c4_0,c4_1
__constant__ float c_bias[17];

__device__ float4 g_pack4[H * 4];      // channels 0..15, [k][p]
__device__ float  g_pack1[H];          // channel 16
__device__ float  g_biasStage[17];
__device__ unsigned int g_ticket;

// ---------------------------------------------------------------------------
__global__ void prep_kernel(
    const float* __restrict__ Wa,  const float* __restrict__ ba,
    const float* __restrict__ Wb,  const float* __restrict__ bb,
    const float* __restrict__ Wc1, const float* __restrict__ bc1,
    const float* __restrict__ Wc2, const float* __restrict__ bc2,
    const float* __restrict__ Wc3, const float* __restrict__ bc3,
    const float* __restrict__ Wc4, const float* __restrict__ bc4)
{
    int id = blockIdx.x * blockDim.x + threadIdx.x;
    if (id == 0) g_ticket = 0u;

    auto getw = [&](int ch, int k) -> float {
        if (ch < 2)  return Wa [ ch        * H + k];
        if (ch < 6)  return Wb [(ch - 2)  * H + k];
        if (ch < 8)  return Wc1[(ch - 6)  * H + k];
        if (ch < 11) return Wc2[(ch - 8)  * H + k];
        if (ch < 15) return Wc3[(ch - 11) * H + k];
        return Wc4[(ch - 15) * H + k];
    };

    if (id < H * 4) {
        int k = id >> 2, p = id & 3;
        g_pack4[id] = make_float4(getw(4 * p, k),     getw(4 * p + 1, k),
                                  getw(4 * p + 2, k), getw(4 * p + 3, k));
    }
    if (id < H) g_pack1[id] = getw(16, id);
    if (id < 17) {
        int ch = id; float b;
        if      (ch < 2)  b = ba [ch];
        else if (ch < 6)  b = bb [ch - 2];
        else if (ch < 8)  b = bc1[ch - 6];
        else if (ch < 11) b = bc2[ch - 8];
        else if (ch < 15) b = bc3[ch - 11];
        else              b = bc4[ch - 15];
        g_biasStage[ch] = b;
    }
}

// ---------------------------------------------------------------------------
__device__ __forceinline__ void ffma2(float2& d, const float2 a, const float2 b)
{
    asm("fma.rn.f32x2 %0, %1, %2, %0;"
        : "+l"(reinterpret_cast<unsigned long long&>(d))
        : "l"(reinterpret_cast<const unsigned long long&>(a)),
          "l"(reinterpret_cast<const unsigned long long&>(b)));
}

__device__ __forceinline__ void cp16(uint32_t saddr, const void* gptr)
{
    asm volatile("cp.async.cg.shared.global [%0], [%1], 16;"
                 :: "r"(saddr), "l"(gptr) : "memory");
}
__device__ __forceinline__ void cp_commit()
{
    asm volatile("cp.async.commit_group;" ::: "memory");
}
template <int N>
__device__ __forceinline__ void cp_wait()
{
    asm volatile("cp.async.wait_group %0;" :: "n"(N) : "memory");
}

// ---------------------------------------------------------------------------
// 128-row pass per warp (4 rows/lane); warp-private 2-deep cp.async ring for x;
// weights in shared memory, explicitly double-buffered into registers across k
// (prefetch spans the chunk barrier); x double-buffered across row-groups.
// 8 warps/SM; warp-level ticket over 1024 passes.
// ---------------------------------------------------------------------------
extern __shared__ float smem[];

__global__ void __launch_bounds__(WARPS * 32)
main_kernel(const float* __restrict__ x, float* __restrict__ out, int B, int npasses)
{
    const int wid  = threadIdx.x >> 5;
    const int lane = threadIdx.x & 31;

    float4* sw    = reinterpret_cast<float4*>(smem);        // [H][5] float4
    float*  xbase = smem + W_FLOATS;

    // ---- stage weights into smem once per CTA ----
    for (int i = threadIdx.x; i < W_SLOTS; i += WARPS * 32) {
        const int k = i / 5, p = i - k * 5;
        sw[i] = (p < 4) ? g_pack4[k * 4 + p]
                        : make_float4(g_pack1[k], 0.f, 0.f, 0.f);
    }
    __syncthreads();

    const uint32_t sb = (uint32_t)__cvta_generic_to_shared(xbase)
                        + wid * (DEPTH * CHUNK_BYTES);
    float* xw = xbase + wid * (DEPTH * CHUNK_FLOATS);

    // cp.async mapping: 4 lanes x 16 B cover one 64 B row segment; 8 rows/inst
    const int crow  = lane >> 2;   // 0..7
    const int cpart = lane & 3;    // 0..3

    for (;;) {
        unsigned t;
        if (lane == 0) t = atomicAdd(&g_ticket, 1u);
        t = __shfl_sync(0xffffffffu, t, 0);
        if (t >= (unsigned)npasses) break;

        const int    row0 = (int)t * WROWS;
        const float* gx   = x + (size_t)row0 * H;

        auto load_chunk = [&](int c, int d) {
            const float*   gsrc = gx + c * CK + (size_t)crow * H + cpart * 4;
            const uint32_t dst0 = sb + d * CHUNK_BYTES + crow * ROWB + cpart * 16;
            #pragma unroll
            for (int i = 0; i < 16; ++i) {         // 16 x 8 rows = 128 rows
                if (row0 + i * 8 + crow < B)
                    cp16(dst0 + i * 8 * ROWB, gsrc + (size_t)(i * 8) * H);
            }
        };

        float2 acc[G][8];
        float  a16[G];
        #pragma unroll
        for (int g = 0; g < G; ++g) {
            #pragma unroll
            for (int p = 0; p < 8; ++p) acc[g][p] = make_float2(0.f, 0.f);
            a16[g] = 0.f;
        }

        cp_wait<0>();                 // drain leftover groups from prior pass
        load_chunk(0, 0); cp_commit();
        load_chunk(1, 1); cp_commit();

        // ---- weight register pipeline: preload k = 0 ----
        float4 wc0, wc1, wc2, wc3; float wcl;
        {
            const float4* p = sw;
            wc0 = p[0]; wc1 = p[1]; wc2 = p[2]; wc3 = p[3]; wcl = p[4].x;
        }

        for (int c = 0; c < NCH; ++c) {
            cp_wait<DEPTH - 1>();     // chunk c resident
            __syncwarp();

            const float* xb = xw + (c & 1) * CHUNK_FLOATS;
            const int kc = c * CK;

            // x register pipeline: preload rg = 0
            float4 xv[G], xvn[G];
            #pragma unroll
            for (int g = 0; g < G; ++g)
                xv[g] = *reinterpret_cast<const float4*>(
                    xb + (lane + 32 * g) * RSTRIDE);

            #pragma unroll
            for (int kk = 0; kk < CK; ++kk) {
                const int rg = kk >> 2;
                const int jj = kk & 3;

                // prefetch next row-group's x at each rg start
                if (jj == 0 && rg < 3) {
                    #pragma unroll
                    for (int g = 0; g < G; ++g)
                        xvn[g] = *reinterpret_cast<const float4*>(
                            xb + (lane + 32 * g) * RSTRIDE + (rg + 1) * 4);
                }

                // prefetch next k's weights (spans the chunk barrier at kk==15)
                const int k  = kc + kk;
                const int kn = (k + 1 < H) ? k + 1 : 0;
                const float4* pn = sw + kn * 5;
                float4 wn0 = pn[0], wn1 = pn[1], wn2 = pn[2], wn3 = pn[3];
                float  wnl = pn[4].x;

                #pragma unroll
                for (int g = 0; g < G; ++g) {
                    const float xk = (jj == 0) ? xv[g].x : (jj == 1) ? xv[g].y
                                   : (jj == 2) ? xv[g].z : xv[g].w;
                    const float2 xd = make_float2(xk, xk);
                    ffma2(acc[g][0], xd, make_float2(wc0.x, wc0.y));
                    ffma2(acc[g][1], xd, make_float2(wc0.z, wc0.w));
                    ffma2(acc[g][2], xd, make_float2(wc1.x, wc1.y));
                    ffma2(acc[g][3], xd, make_float2(wc1.z, wc1.w));
                    ffma2(acc[g][4], xd, make_float2(wc2.x, wc2.y));
                    ffma2(acc[g][5], xd, make_float2(wc2.z, wc2.w));
                    ffma2(acc[g][6], xd, make_float2(wc3.x, wc3.y));
                    ffma2(acc[g][7], xd, make_float2(wc3.z, wc3.w));
                    a16[g] = fmaf(xk, wcl, a16[g]);
                }

                wc0 = wn0; wc1 = wn1; wc2 = wn2; wc3 = wn3; wcl = wnl;

                if (jj == 3 && rg < 3) {
                    #pragma unroll
                    for (int g = 0; g < G; ++g) xv[g] = xvn[g];
                }
            }
            __syncwarp();

            if (c + DEPTH < NCH) load_chunk(c + DEPTH, c & 1);
            cp_commit();              // empty groups keep wait_group counts exact
        }

        // --- epilogue: bias, routing, masked scattered stores (4 rows/lane) ---
        #pragma unroll
        for (int g = 0; g < G; ++g) {
            const int r = row0 + lane + 32 * g;
            if (r >= B) continue;

            float v[17];
            #pragma unroll
            for (int p = 0; p < 8; ++p) {
                v[2 * p]     = acc[g][p].x + c_bias[2 * p];
                v[2 * p + 1] = acc[g][p].y + c_bias[2 * p + 1];
            }
            v[16] = a16[g] + c_bias[16];

            const bool active = v[1] > v[0];               // argmax(out_a) != 0

            ((float2*)out)[r] = make_float2(v[0], v[1]);   // out_a

            int pb = 0; float best = v[2];
            if (v[3] > best) { pb = 1; best = v[3]; }
            if (v[4] > best) { pb = 2; best = v[4]; }
            if (v[5] > best) { pb = 3; best = v[5]; }

            float* ob = out + 2 * (size_t)B + 5 * (size_t)r;   // out_b
            ob[0] = 0.0f;
            #pragma unroll
            for (int j = 0; j < 4; ++j) ob[j + 1] = active ? v[2 + j] : 0.0f;

            float* oc = out + 7 * (size_t)B + 11 * (size_t)r;  // out_c
            #pragma unroll
            for (int j = 0; j < 11; ++j) {
                const int hd = (j < 2) ? 0 : (j < 5) ? 1 : (j < 9) ? 2 : 3;
                oc[j] = (active && hd == pb) ? v[6 + j] : 0.0f;
            }
        }
    }
}

// ---------------------------------------------------------------------------
extern "C" void kernel_launch(void* const* d_in, const int* in_sizes, int n_in,
                              void* d_out, int out_size)
{
    const float* x = (const float*)d_in[0];
    const int B = in_sizes[0] / H;

    prep_kernel<<<12, 256>>>(
        (const float*)d_in[1],  (const float*)d_in[2],
        (const float*)d_in[3],  (const float*)d_in[4],
        (const float*)d_in[5],  (const float*)d_in[6],
        (const float*)d_in[7],  (const float*)d_in[8],
        (const float*)d_in[9],  (const float*)d_in[10],
        (const float*)d_in[11], (const float*)d_in[12]);

    void* pb = nullptr; cudaGetSymbolAddress(&pb, g_biasStage);
    cudaMemcpyToSymbolAsync(c_bias, pb, sizeof(float) * 17, 0,
                            cudaMemcpyDeviceToDevice, 0);

    const int npasses = (B + WROWS - 1) / WROWS;   // 1024 for B=131072
    const int grid    = 148;                        // 1 CTA/SM

    cudaFuncSetAttribute(main_kernel,
                         cudaFuncAttributeMaxDynamicSharedMemorySize, SMEM_BYTES);
    main_kernel<<<grid, WARPS * 32, SMEM_BYTES>>>(x, (float*)d_out, B, npasses);
}